// round 1
// baseline (speedup 1.0000x reference)
#include <cuda_runtime.h>
#include <math.h>

#define Bq 16
#define Sq 2048
#define Hq 512
#define Oq 16
#define BSq (Bq*Sq)            // 32768
#define RSQRT_H 0.04419417382415922f   // 1/sqrt(512)

// ---------------- scratch (device globals; no allocation allowed) ----------
__device__ float g_oq[Oq*Hq];          // raw operator queries (atomic accum)
__device__ float g_kq[Oq*Hq];          // oq @ Wk, pre-scaled by 1/sqrt(H)
__device__ float g_c[Oq];              // bk . oq, pre-scaled
__device__ float g_logits[BSq*Oq];     // [b][s][o]
__device__ float g_w[BSq*Oq];          // rw * operators, [b][s][o]
__device__ float g_W[Bq*Oq];           // sum_s w
__device__ float g_u[Bq*Oq*Hq];        // sum_s w * x  (atomic accum)
__device__ float g_opout[Bq*Oq*Hq];    // operator outputs

// ---------------- K-zero: clear accumulators -------------------------------
__global__ void kzero() {
    int i = blockIdx.x * 256 + threadIdx.x;
    if (i < Bq*Oq*Hq) g_u[i] = 0.f;
    if (i < Oq*Hq)    g_oq[i] = 0.f;
}

// ---------------- K0a: oq[o][h] = sum_s ops[s][o] * Wq_op[h][s] ------------
// grid (8 h-tiles of 64, 16 s-chunks of 128), 512 threads
__global__ void __launch_bounds__(512) k0a(const float* __restrict__ Wq_op,
                                           const float* __restrict__ ops) {
    __shared__ float ops_sh[128*16];
    __shared__ float wq_sh[64][129];
    int h0 = blockIdx.x * 64, s0 = blockIdx.y * 128;
    for (int i = threadIdx.x; i < 128*16; i += 512)
        ops_sh[i] = ops[s0*16 + i];
    for (int i = threadIdx.x; i < 64*128; i += 512) {
        int r = i >> 7, c = i & 127;
        wq_sh[r][c] = Wq_op[(size_t)(h0 + r)*Sq + s0 + c];
    }
    __syncthreads();
    int hl = threadIdx.x & 63;
    int og = threadIdx.x >> 6;         // 0..7 -> owns o = 2*og, 2*og+1
    float a0 = 0.f, a1 = 0.f;
    #pragma unroll 8
    for (int s = 0; s < 128; s++) {
        float wv = wq_sh[hl][s];
        a0 += wv * ops_sh[s*16 + og*2];
        a1 += wv * ops_sh[s*16 + og*2 + 1];
    }
    atomicAdd(&g_oq[(og*2    )*Hq + h0 + hl], a0);
    atomicAdd(&g_oq[(og*2 + 1)*Hq + h0 + hl], a1);
}

// ---------------- K0b: finalize oq (+bias, export), kq = oq@Wk, c = bk.oq --
// grid 16 (one per o), 256 threads
__global__ void __launch_bounds__(256) k0b(const float* __restrict__ Wk,
                                           const float* __restrict__ bk,
                                           const float* __restrict__ bq,
                                           float* oq_out) {
    __shared__ float oq_sh[Hq];
    __shared__ float cred[256];
    int o = blockIdx.x;
    for (int h = threadIdx.x; h < Hq; h += 256) {
        float v = g_oq[o*Hq + h] + bq[h];
        oq_sh[h] = v;
        if (oq_out) oq_out[o*Hq + h] = v;
    }
    __syncthreads();
    for (int k = threadIdx.x; k < Hq; k += 256) {
        float a = 0.f;
        #pragma unroll 4
        for (int h = 0; h < Hq; h++)
            a += oq_sh[h] * Wk[(size_t)h*Hq + k];
        g_kq[o*Hq + k] = a * RSQRT_H;
    }
    float cl = 0.f;
    for (int h = threadIdx.x; h < Hq; h += 256) cl += bk[h] * oq_sh[h];
    cred[threadIdx.x] = cl;
    __syncthreads();
    for (int st = 128; st > 0; st >>= 1) {
        if (threadIdx.x < st) cred[threadIdx.x] += cred[threadIdx.x + st];
        __syncthreads();
    }
    if (threadIdx.x == 0) g_c[o] = cred[0] * RSQRT_H;
}

// ---------------- K1: logits[b,s,o] = x[b,s,:].kq[o,:] + c[o] --------------
// warp handles 4 rows; kq resident in smem (32KB). grid 1024, 256 threads
__global__ void __launch_bounds__(256) k1(const float* __restrict__ x) {
    __shared__ float4 kq4[Oq*128];
    __shared__ float c_sh[Oq];
    for (int i = threadIdx.x; i < Oq*128; i += 256)
        kq4[i] = ((const float4*)g_kq)[i];
    if (threadIdx.x < Oq) c_sh[threadIdx.x] = g_c[threadIdx.x];
    __syncthreads();
    int wid = threadIdx.x >> 5, lane = threadIdx.x & 31;
    int r0 = blockIdx.x * 32 + wid * 4;
    const float4* xr = ((const float4*)x) + (size_t)r0 * 128;
    float acc[4][16];
    #pragma unroll
    for (int r = 0; r < 4; r++)
        #pragma unroll
        for (int o = 0; o < 16; o++) acc[r][o] = 0.f;
    #pragma unroll
    for (int jj = 0; jj < 4; jj++) {
        int j = jj * 32 + lane;
        float4 x0 = xr[j], x1 = xr[128 + j], x2 = xr[256 + j], x3 = xr[384 + j];
        #pragma unroll
        for (int o = 0; o < 16; o++) {
            float4 kv = kq4[o*128 + j];
            acc[0][o] += x0.x*kv.x + x0.y*kv.y + x0.z*kv.z + x0.w*kv.w;
            acc[1][o] += x1.x*kv.x + x1.y*kv.y + x1.z*kv.z + x1.w*kv.w;
            acc[2][o] += x2.x*kv.x + x2.y*kv.y + x2.z*kv.z + x2.w*kv.w;
            acc[3][o] += x3.x*kv.x + x3.y*kv.y + x3.z*kv.z + x3.w*kv.w;
        }
    }
    #pragma unroll
    for (int r = 0; r < 4; r++)
        #pragma unroll
        for (int o = 0; o < 16; o++) {
            float v = acc[r][o];
            v += __shfl_down_sync(0xffffffffu, v, 16);
            v += __shfl_down_sync(0xffffffffu, v, 8);
            v += __shfl_down_sync(0xffffffffu, v, 4);
            v += __shfl_down_sync(0xffffffffu, v, 2);
            v += __shfl_down_sync(0xffffffffu, v, 1);
            acc[r][o] = v;
        }
    if (lane == 0) {
        float4* Lp = (float4*)(g_logits + (size_t)r0 * 16);
        #pragma unroll
        for (int r = 0; r < 4; r++) {
            Lp[r*4+0] = make_float4(acc[r][0]+c_sh[0],  acc[r][1]+c_sh[1],
                                    acc[r][2]+c_sh[2],  acc[r][3]+c_sh[3]);
            Lp[r*4+1] = make_float4(acc[r][4]+c_sh[4],  acc[r][5]+c_sh[5],
                                    acc[r][6]+c_sh[6],  acc[r][7]+c_sh[7]);
            Lp[r*4+2] = make_float4(acc[r][8]+c_sh[8],  acc[r][9]+c_sh[9],
                                    acc[r][10]+c_sh[10],acc[r][11]+c_sh[11]);
            Lp[r*4+3] = make_float4(acc[r][12]+c_sh[12],acc[r][13]+c_sh[13],
                                    acc[r][14]+c_sh[14],acc[r][15]+c_sh[15]);
        }
    }
}

// ---------------- K1b: softmax over s -> w = rw*ops, W = sum_s w -----------
// grid 16 (per b), 512 threads; fully coalesced (o = tid & 15 is fixed/thread)
__global__ void __launch_bounds__(512) k1b(const float* __restrict__ ops) {
    int b = blockIdx.x;
    const float* L = g_logits + (size_t)b * (Sq*Oq);
    int tid = threadIdx.x, lane = tid & 31, wid = tid >> 5;
    int o = tid & 15;
    __shared__ float red[16][16];
    __shared__ float s_mx[16], s_sum[16];

    // pass 1: max over s per o
    float mx = -1e30f;
    for (int i = tid; i < Sq*Oq; i += 512) mx = fmaxf(mx, L[i]);
    mx = fmaxf(mx, __shfl_xor_sync(0xffffffffu, mx, 16));
    if (lane < 16) red[wid][lane] = mx;
    __syncthreads();
    if (tid < 16) {
        float m = red[0][tid];
        #pragma unroll
        for (int w = 1; w < 16; w++) m = fmaxf(m, red[w][tid]);
        s_mx[tid] = m;
    }
    __syncthreads();
    float m = s_mx[o];

    // pass 2: sum of exp
    float sm = 0.f;
    for (int i = tid; i < Sq*Oq; i += 512) sm += __expf(L[i] - m);
    sm += __shfl_xor_sync(0xffffffffu, sm, 16);
    __syncthreads();
    if (lane < 16) red[wid][lane] = sm;
    __syncthreads();
    if (tid < 16) {
        float s = red[0][tid];
        #pragma unroll
        for (int w = 1; w < 16; w++) s += red[w][tid];
        s_sum[tid] = s;
    }
    __syncthreads();
    float inv = 1.0f / s_sum[o];

    // pass 3: w = rw * ops;  W = sum_s w
    float Wl = 0.f;
    float* wout = g_w + (size_t)b * (Sq*Oq);
    for (int i = tid; i < Sq*Oq; i += 512) {
        float wv = __expf(L[i] - m) * inv * ops[i];   // i == s*16+o matches ops layout
        wout[i] = wv;
        Wl += wv;
    }
    Wl += __shfl_xor_sync(0xffffffffu, Wl, 16);
    __syncthreads();
    if (lane < 16) red[wid][lane] = Wl;
    __syncthreads();
    if (tid < 16) {
        float s = red[0][tid];
        #pragma unroll
        for (int w = 1; w < 16; w++) s += red[w][tid];
        g_W[b*16 + tid] = s;
    }
}

// ---------------- K2: u[b,o,k] = sum_s w[b,s,o]*x[b,s,k] (split-s atomics) -
// grid (4 k-chunks, 8 s-chunks, 16 b), 128 threads
__global__ void __launch_bounds__(128) k2(const float* __restrict__ x) {
    int k = blockIdx.x * 128 + threadIdx.x;
    int b = blockIdx.z, s0 = blockIdx.y * 256;
    const float* xp = x + ((size_t)b*Sq + s0) * Hq + k;
    const float4* wp = (const float4*)(g_w + ((size_t)b*Sq + s0) * 16);
    float acc[16];
    #pragma unroll
    for (int o = 0; o < 16; o++) acc[o] = 0.f;
    #pragma unroll 2
    for (int s = 0; s < 256; s++) {
        float xv = xp[(size_t)s * Hq];
        float4 w0 = wp[s*4], w1 = wp[s*4+1], w2 = wp[s*4+2], w3 = wp[s*4+3];
        acc[0]  += w0.x*xv; acc[1]  += w0.y*xv; acc[2]  += w0.z*xv; acc[3]  += w0.w*xv;
        acc[4]  += w1.x*xv; acc[5]  += w1.y*xv; acc[6]  += w1.z*xv; acc[7]  += w1.w*xv;
        acc[8]  += w2.x*xv; acc[9]  += w2.y*xv; acc[10] += w2.z*xv; acc[11] += w2.w*xv;
        acc[12] += w3.x*xv; acc[13] += w3.y*xv; acc[14] += w3.z*xv; acc[15] += w3.w*xv;
    }
    #pragma unroll
    for (int o = 0; o < 16; o++)
        atomicAdd(&g_u[((size_t)b*16 + o)*Hq + k], acc[o]);
}

// ---------------- K3: op_out[b,o,h] = u[b,o,:].Wv[h,:] + bv[h]*W[b,o] ------
// grid (16 o, 16 h-chunks of 32), 128 threads (4 warps, 4 h per warp-quad)
__global__ void __launch_bounds__(128) k3(const float* __restrict__ Wv,
                                          const float* __restrict__ bv) {
    __shared__ float4 u4[16*128];   // u[b][k] for this o
    __shared__ float Wsh[16];
    int o = blockIdx.x, hc = blockIdx.y;
    for (int i = threadIdx.x; i < 16*128; i += 128) {
        int b = i >> 7, k4 = i & 127;
        u4[i] = ((const float4*)g_u)[((size_t)b*16 + o)*128 + k4];
    }
    if (threadIdx.x < 16) Wsh[threadIdx.x] = g_W[threadIdx.x*16 + o];
    __syncthreads();
    int wid = threadIdx.x >> 5, lane = threadIdx.x & 31;
    for (int q = 0; q < 2; q++) {
        int h = hc*32 + wid*8 + q*4;
        const float4* wv = ((const float4*)Wv) + (size_t)h * 128;
        float acc[4][16];
        #pragma unroll
        for (int r = 0; r < 4; r++)
            #pragma unroll
            for (int b = 0; b < 16; b++) acc[r][b] = 0.f;
        #pragma unroll
        for (int jj = 0; jj < 4; jj++) {
            int j = jj*32 + lane;
            float4 v0 = wv[j], v1 = wv[128+j], v2 = wv[256+j], v3 = wv[384+j];
            #pragma unroll
            for (int b = 0; b < 16; b++) {
                float4 uu = u4[b*128 + j];
                acc[0][b] += v0.x*uu.x + v0.y*uu.y + v0.z*uu.z + v0.w*uu.w;
                acc[1][b] += v1.x*uu.x + v1.y*uu.y + v1.z*uu.z + v1.w*uu.w;
                acc[2][b] += v2.x*uu.x + v2.y*uu.y + v2.z*uu.z + v2.w*uu.w;
                acc[3][b] += v3.x*uu.x + v3.y*uu.y + v3.z*uu.z + v3.w*uu.w;
            }
        }
        #pragma unroll
        for (int r = 0; r < 4; r++)
            #pragma unroll
            for (int b = 0; b < 16; b++) {
                float v = acc[r][b];
                v += __shfl_down_sync(0xffffffffu, v, 16);
                v += __shfl_down_sync(0xffffffffu, v, 8);
                v += __shfl_down_sync(0xffffffffu, v, 4);
                v += __shfl_down_sync(0xffffffffu, v, 2);
                v += __shfl_down_sync(0xffffffffu, v, 1);
                acc[r][b] = v;
            }
        if (lane == 0) {
            #pragma unroll
            for (int r = 0; r < 4; r++) {
                float bvh = bv[h + r];
                #pragma unroll
                for (int b = 0; b < 16; b++)
                    g_opout[((size_t)b*16 + o)*Hq + h + r] = acc[r][b] + bvh * Wsh[b];
            }
        }
    }
}

// ---------------- K4: out[b,s,h] = sum_o softmax_o(logits)[o]*op_out[b,o,h]
// grid (32 s-chunks of 64, 16 b), 256 threads; op_out[b] in smem
__global__ void __launch_bounds__(256) k4(float* __restrict__ out) {
    __shared__ float4 op4[16*128];
    int b = blockIdx.y, sc = blockIdx.x;
    for (int i = threadIdx.x; i < 16*128; i += 256)
        op4[i] = ((const float4*)g_opout)[(size_t)b*2048 + i];
    __syncthreads();
    int wid = threadIdx.x >> 5, lane = threadIdx.x & 31;
    for (int q = 0; q < 2; q++) {
        int s0 = sc*64 + wid*8 + q*4;
        size_t r0 = (size_t)b*Sq + s0;
        // lane computes softmax of row r0 + (lane&3), then broadcast within quads
        const float* lp = g_logits + (r0 + (lane & 3)) * 16;
        float e[16];
        float mx = -1e30f;
        #pragma unroll
        for (int o = 0; o < 16; o++) { e[o] = lp[o]; mx = fmaxf(mx, e[o]); }
        float sum = 0.f;
        #pragma unroll
        for (int o = 0; o < 16; o++) { e[o] = __expf(e[o] - mx); sum += e[o]; }
        float inv = 1.0f / sum;
        float ow0[16], ow1[16], ow2[16], ow3[16];
        #pragma unroll
        for (int o = 0; o < 16; o++) {
            float v = e[o] * inv;
            ow0[o] = __shfl_sync(0xffffffffu, v, 0, 4);
            ow1[o] = __shfl_sync(0xffffffffu, v, 1, 4);
            ow2[o] = __shfl_sync(0xffffffffu, v, 2, 4);
            ow3[o] = __shfl_sync(0xffffffffu, v, 3, 4);
        }
        float4* out4 = ((float4*)out) + r0 * 128;
        #pragma unroll
        for (int jj = 0; jj < 4; jj++) {
            int j = jj*32 + lane;
            float4 a0 = {0,0,0,0}, a1 = {0,0,0,0}, a2 = {0,0,0,0}, a3 = {0,0,0,0};
            #pragma unroll
            for (int o = 0; o < 16; o++) {
                float4 kv = op4[o*128 + j];
                a0.x += ow0[o]*kv.x; a0.y += ow0[o]*kv.y; a0.z += ow0[o]*kv.z; a0.w += ow0[o]*kv.w;
                a1.x += ow1[o]*kv.x; a1.y += ow1[o]*kv.y; a1.z += ow1[o]*kv.z; a1.w += ow1[o]*kv.w;
                a2.x += ow2[o]*kv.x; a2.y += ow2[o]*kv.y; a2.z += ow2[o]*kv.z; a2.w += ow2[o]*kv.w;
                a3.x += ow3[o]*kv.x; a3.y += ow3[o]*kv.y; a3.z += ow3[o]*kv.z; a3.w += ow3[o]*kv.w;
            }
            out4[j] = a0; out4[128 + j] = a1; out4[256 + j] = a2; out4[384 + j] = a3;
        }
    }
}

// ---------------------------------------------------------------------------
extern "C" void kernel_launch(void* const* d_in, const int* in_sizes, int n_in,
                              void* d_out, int out_size) {
    const float* x     = (const float*)d_in[0];
    const float* Wv    = (const float*)d_in[1];
    const float* bv    = (const float*)d_in[2];
    const float* Wk    = (const float*)d_in[3];
    const float* bk    = (const float*)d_in[4];
    const float* Wq_op = (const float*)d_in[5];
    const float* bq_op = (const float*)d_in[6];
    const float* ops   = (const float*)d_in[7];
    (void)in_sizes; (void)n_in;
    float* out = (float*)d_out;
    float* oq_out = (out_size >= Bq*Sq*Hq + Oq*Hq) ? out + (size_t)Bq*Sq*Hq : nullptr;

    kzero<<<512, 256>>>();
    k0a<<<dim3(8, 16), 512>>>(Wq_op, ops);
    k0b<<<Oq, 256>>>(Wk, bk, bq_op, oq_out);
    k1<<<BSq/32, 256>>>(x);
    k1b<<<Bq, 512>>>(ops);
    k2<<<dim3(4, 8, 16), 128>>>(x);
    k3<<<dim3(16, 16), 128>>>(Wv, bv);
    k4<<<dim3(32, 16), 256>>>(out);
}

// round 2
// speedup vs baseline: 1.4132x; 1.4132x over previous
#include <cuda_runtime.h>
#include <math.h>

#define Bq 16
#define Sq 2048
#define Hq 512
#define Oq 16
#define BSq (Bq*Sq)            // 32768
#define RSQRT_H 0.04419417382415922f   // 1/sqrt(512)

typedef unsigned long long ull;

__device__ __forceinline__ ull ffma2(ull a, ull b, ull c) {
    ull d;
    asm("fma.rn.f32x2 %0, %1, %2, %3;" : "=l"(d) : "l"(a), "l"(b), "l"(c));
    return d;
}

// ---------------- scratch (device globals; no allocation allowed) ----------
__device__ float g_oq[Oq*Hq];          // raw operator queries (atomic accum)
__device__ float g_kq[Oq*Hq];          // oq @ Wk, pre-scaled by 1/sqrt(H)
__device__ float g_c[Oq];              // bk . oq, pre-scaled
__device__ float g_logits[BSq*Oq];     // [b][s][o]
__device__ float g_esum[Bq*Oq];        // sum_s exp(logits)  (atomic accum)
__device__ float g_W[Bq*Oq];           // sum_s w            (atomic accum)
__device__ float g_up[8*Bq*Oq*Hq];     // split-s partials of u
__device__ float g_u[Bq*Oq*Hq];        // sum_s w * x
__device__ float g_opout[Bq*Oq*Hq];    // operator outputs

// ---------------- K-zero: clear accumulators -------------------------------
__global__ void kzero() {
    int i = blockIdx.x * 256 + threadIdx.x;
    if (i < Oq*Hq) g_oq[i] = 0.f;
    if (i < Bq*Oq) { g_esum[i] = 0.f; g_W[i] = 0.f; }
}

// ---------------- K0a: oq[o][h] = sum_s ops[s][o] * Wq_op[h][s] ------------
__global__ void __launch_bounds__(512) k0a(const float* __restrict__ Wq_op,
                                           const float* __restrict__ ops) {
    __shared__ float ops_sh[128*16];
    __shared__ float wq_sh[64][129];
    int h0 = blockIdx.x * 64, s0 = blockIdx.y * 128;
    for (int i = threadIdx.x; i < 128*16; i += 512)
        ops_sh[i] = ops[s0*16 + i];
    for (int i = threadIdx.x; i < 64*128; i += 512) {
        int r = i >> 7, c = i & 127;
        wq_sh[r][c] = Wq_op[(size_t)(h0 + r)*Sq + s0 + c];
    }
    __syncthreads();
    int hl = threadIdx.x & 63;
    int og = threadIdx.x >> 6;
    float a0 = 0.f, a1 = 0.f;
    #pragma unroll 8
    for (int s = 0; s < 128; s++) {
        float wv = wq_sh[hl][s];
        a0 += wv * ops_sh[s*16 + og*2];
        a1 += wv * ops_sh[s*16 + og*2 + 1];
    }
    atomicAdd(&g_oq[(og*2    )*Hq + h0 + hl], a0);
    atomicAdd(&g_oq[(og*2 + 1)*Hq + h0 + hl], a1);
}

// ---------------- K0b: kq = (oq+bq)@Wk * rsqrtH; c = bk.(oq+bq) * rsqrtH ---
// grid (16 o, 4 k-chunks), 128 threads
__global__ void __launch_bounds__(128) k0b(const float* __restrict__ Wk,
                                           const float* __restrict__ bk,
                                           const float* __restrict__ bq,
                                           float* oq_out) {
    __shared__ float oq_sh[Hq];
    __shared__ float cr[128];
    int o = blockIdx.x, kc = blockIdx.y;
    for (int h = threadIdx.x; h < Hq; h += 128) {
        float v = g_oq[o*Hq + h] + bq[h];
        oq_sh[h] = v;
        if (kc == 0 && oq_out) oq_out[o*Hq + h] = v;
    }
    __syncthreads();
    int k = kc*128 + threadIdx.x;
    float a = 0.f;
    #pragma unroll 16
    for (int h = 0; h < Hq; h++)
        a += oq_sh[h] * Wk[(size_t)h*Hq + k];
    g_kq[o*Hq + k] = a * RSQRT_H;
    if (kc == 0) {
        float cl = 0.f;
        for (int h = threadIdx.x; h < Hq; h += 128) cl += bk[h] * oq_sh[h];
        cr[threadIdx.x] = cl;
        __syncthreads();
        for (int st = 64; st > 0; st >>= 1) {
            if (threadIdx.x < st) cr[threadIdx.x] += cr[threadIdx.x + st];
            __syncthreads();
        }
        if (threadIdx.x == 0) g_c[o] = cr[0] * RSQRT_H;
    }
}

// ---------------- K1: logits[b,s,o] = x[b,s,:].kq[o,:] + c[o]; fused esum --
// warp handles 4 rows; kq in smem. grid 1024, 256 threads (32 rows/block)
__global__ void __launch_bounds__(256) k1(const float* __restrict__ x) {
    __shared__ float4 kq4[Oq*128];
    __shared__ float c_sh[Oq];
    __shared__ float st[32*16];
    __shared__ float esr[16][17];
    for (int i = threadIdx.x; i < Oq*128; i += 256)
        kq4[i] = ((const float4*)g_kq)[i];
    if (threadIdx.x < Oq) c_sh[threadIdx.x] = g_c[threadIdx.x];
    __syncthreads();
    int wid = threadIdx.x >> 5, lane = threadIdx.x & 31;
    int r0 = blockIdx.x * 32 + wid * 4;
    const float4* xr = ((const float4*)x) + (size_t)r0 * 128;
    float acc[4][16];
    #pragma unroll
    for (int r = 0; r < 4; r++)
        #pragma unroll
        for (int o = 0; o < 16; o++) acc[r][o] = 0.f;
    #pragma unroll
    for (int jj = 0; jj < 4; jj++) {
        int j = jj * 32 + lane;
        float4 x0 = xr[j], x1 = xr[128 + j], x2 = xr[256 + j], x3 = xr[384 + j];
        #pragma unroll
        for (int o = 0; o < 16; o++) {
            float4 kv = kq4[o*128 + j];
            acc[0][o] += x0.x*kv.x + x0.y*kv.y + x0.z*kv.z + x0.w*kv.w;
            acc[1][o] += x1.x*kv.x + x1.y*kv.y + x1.z*kv.z + x1.w*kv.w;
            acc[2][o] += x2.x*kv.x + x2.y*kv.y + x2.z*kv.z + x2.w*kv.w;
            acc[3][o] += x3.x*kv.x + x3.y*kv.y + x3.z*kv.z + x3.w*kv.w;
        }
    }
    #pragma unroll
    for (int r = 0; r < 4; r++)
        #pragma unroll
        for (int o = 0; o < 16; o++) {
            float v = acc[r][o];
            v += __shfl_down_sync(0xffffffffu, v, 16);
            v += __shfl_down_sync(0xffffffffu, v, 8);
            v += __shfl_down_sync(0xffffffffu, v, 4);
            v += __shfl_down_sync(0xffffffffu, v, 2);
            v += __shfl_down_sync(0xffffffffu, v, 1);
            acc[r][o] = v;
        }
    if (lane == 0) {
        #pragma unroll
        for (int r = 0; r < 4; r++)
            #pragma unroll
            for (int o = 0; o < 16; o++)
                st[(wid*4 + r)*16 + o] = acc[r][o] + c_sh[o];
    }
    __syncthreads();
    // coalesced logits store + exp-sum
    float v0 = st[threadIdx.x];
    float v1 = st[threadIdx.x + 256];
    size_t gbase = (size_t)blockIdx.x * 512;
    g_logits[gbase + threadIdx.x]       = v0;
    g_logits[gbase + threadIdx.x + 256] = v1;
    float ep = __expf(v0) + __expf(v1);
    esr[threadIdx.x >> 4][threadIdx.x & 15] = ep;
    __syncthreads();
    if (threadIdx.x < 16) {
        float s = 0.f;
        #pragma unroll
        for (int j = 0; j < 16; j++) s += esr[j][threadIdx.x];
        int b = blockIdx.x >> 6;    // 32 rows/block, 2048 rows/b
        atomicAdd(&g_esum[b*16 + threadIdx.x], s);
    }
}

// ---------------- K2: split-s partials of u = sum_s w*x; w built in smem ---
// grid (8 s-chunks, 16 b), 256 threads; thread owns k=tid, tid+256
__global__ void __launch_bounds__(256) k2(const float* __restrict__ x,
                                          const float* __restrict__ ops) {
    __shared__ float4 w4[256*4];       // 16KB, w[s][o], 16B-aligned for ull LDS
    __shared__ float inv_sh[16];
    __shared__ float wr[16][17];
    float* w_sh = (float*)w4;
    int sc = blockIdx.x, b = blockIdx.y;
    int tid = threadIdx.x;
    int s0 = sc * 256;
    if (tid < 16) inv_sh[tid] = 1.0f / g_esum[b*16 + tid];
    __syncthreads();
    const float* L  = g_logits + ((size_t)b*Sq + s0)*16;
    const float* op = ops + (size_t)s0*16;
    float Wloc = 0.f;
    #pragma unroll
    for (int t = 0; t < 16; t++) {
        int i = t*256 + tid;
        float wv = __expf(L[i]) * inv_sh[i & 15] * op[i];
        w_sh[i] = wv;
        Wloc += wv;
    }
    wr[tid >> 4][tid & 15] = Wloc;
    __syncthreads();
    if (tid < 16) {
        float s = 0.f;
        #pragma unroll
        for (int j = 0; j < 16; j++) s += wr[j][tid];
        atomicAdd(&g_W[b*16 + tid], s);
    }
    // main accumulation, f32x2 packed over o-pairs
    const float* xq = x + ((size_t)b*Sq + s0)*Hq + tid;
    ull acc0[8], acc1[8];
    #pragma unroll
    for (int j = 0; j < 8; j++) { acc0[j] = 0ull; acc1[j] = 0ull; }
    #pragma unroll 8
    for (int s = 0; s < 256; s++) {
        float xv0 = xq[(size_t)s*Hq];
        float xv1 = xq[(size_t)s*Hq + 256];
        ull xa, xb;
        asm("mov.b64 %0, {%1,%1};" : "=l"(xa) : "f"(xv0));
        asm("mov.b64 %0, {%1,%1};" : "=l"(xb) : "f"(xv1));
        const ull* w8 = (const ull*)(w_sh + s*16);
        #pragma unroll
        for (int j = 0; j < 8; j++) {
            ull wv = w8[j];
            acc0[j] = ffma2(xa, wv, acc0[j]);
            acc1[j] = ffma2(xb, wv, acc1[j]);
        }
    }
    float* up = g_up + (size_t)(sc*16 + b)*16*512;
    #pragma unroll
    for (int j = 0; j < 8; j++) {
        float lo, hi;
        asm("mov.b64 {%0,%1}, %2;" : "=f"(lo), "=f"(hi) : "l"(acc0[j]));
        up[(2*j)*512 + tid]         = lo;
        up[(2*j+1)*512 + tid]       = hi;
        asm("mov.b64 {%0,%1}, %2;" : "=f"(lo), "=f"(hi) : "l"(acc1[j]));
        up[(2*j)*512 + tid + 256]   = lo;
        up[(2*j+1)*512 + tid + 256] = hi;
    }
}

// ---------------- Ksum: u = sum of 8 split-s partials -----------------------
__global__ void ksum() {
    int i = blockIdx.x*256 + threadIdx.x;   // 32768 float4s
    const float4* up4 = (const float4*)g_up;
    float4 s = up4[i];
    #pragma unroll
    for (int p = 1; p < 8; p++) {
        float4 t = up4[p*32768 + i];
        s.x += t.x; s.y += t.y; s.z += t.z; s.w += t.w;
    }
    ((float4*)g_u)[i] = s;
}

// ---------------- K3: op_out[b,o,h] = u[b,o,:].Wv[h,:] + bv[h]*W[b,o] ------
__global__ void __launch_bounds__(128) k3(const float* __restrict__ Wv,
                                          const float* __restrict__ bv) {
    __shared__ float4 u4[16*128];
    __shared__ float Wsh[16];
    int o = blockIdx.x, hc = blockIdx.y;
    for (int i = threadIdx.x; i < 16*128; i += 128) {
        int b = i >> 7, k4 = i & 127;
        u4[i] = ((const float4*)g_u)[((size_t)b*16 + o)*128 + k4];
    }
    if (threadIdx.x < 16) Wsh[threadIdx.x] = g_W[threadIdx.x*16 + o];
    __syncthreads();
    int wid = threadIdx.x >> 5, lane = threadIdx.x & 31;
    for (int q = 0; q < 2; q++) {
        int h = hc*32 + wid*8 + q*4;
        const float4* wv = ((const float4*)Wv) + (size_t)h * 128;
        float acc[4][16];
        #pragma unroll
        for (int r = 0; r < 4; r++)
            #pragma unroll
            for (int b = 0; b < 16; b++) acc[r][b] = 0.f;
        #pragma unroll
        for (int jj = 0; jj < 4; jj++) {
            int j = jj*32 + lane;
            float4 v0 = wv[j], v1 = wv[128+j], v2 = wv[256+j], v3 = wv[384+j];
            #pragma unroll
            for (int b = 0; b < 16; b++) {
                float4 uu = u4[b*128 + j];
                acc[0][b] += v0.x*uu.x + v0.y*uu.y + v0.z*uu.z + v0.w*uu.w;
                acc[1][b] += v1.x*uu.x + v1.y*uu.y + v1.z*uu.z + v1.w*uu.w;
                acc[2][b] += v2.x*uu.x + v2.y*uu.y + v2.z*uu.z + v2.w*uu.w;
                acc[3][b] += v3.x*uu.x + v3.y*uu.y + v3.z*uu.z + v3.w*uu.w;
            }
        }
        #pragma unroll
        for (int r = 0; r < 4; r++)
            #pragma unroll
            for (int b = 0; b < 16; b++) {
                float v = acc[r][b];
                v += __shfl_down_sync(0xffffffffu, v, 16);
                v += __shfl_down_sync(0xffffffffu, v, 8);
                v += __shfl_down_sync(0xffffffffu, v, 4);
                v += __shfl_down_sync(0xffffffffu, v, 2);
                v += __shfl_down_sync(0xffffffffu, v, 1);
                acc[r][b] = v;
            }
        if (lane == 0) {
            #pragma unroll
            for (int r = 0; r < 4; r++) {
                float bvh = bv[h + r];
                #pragma unroll
                for (int b = 0; b < 16; b++)
                    g_opout[((size_t)b*16 + o)*Hq + h + r] = acc[r][b] + bvh * Wsh[b];
            }
        }
    }
}

// ---------------- K4: out[b,s,h] = sum_o softmax_o(logits)[o]*op_out[b,o,h]
__global__ void __launch_bounds__(256) k4(float* __restrict__ out) {
    __shared__ float4 op4[16*128];
    int b = blockIdx.y, sc = blockIdx.x;
    for (int i = threadIdx.x; i < 16*128; i += 256)
        op4[i] = ((const float4*)g_opout)[(size_t)b*2048 + i];
    __syncthreads();
    int wid = threadIdx.x >> 5, lane = threadIdx.x & 31;
    for (int q = 0; q < 2; q++) {
        int s0 = sc*64 + wid*8 + q*4;
        size_t r0 = (size_t)b*Sq + s0;
        const float* lp = g_logits + (r0 + (lane & 3)) * 16;
        float e[16];
        float mx = -1e30f;
        #pragma unroll
        for (int o = 0; o < 16; o++) { e[o] = lp[o]; mx = fmaxf(mx, e[o]); }
        float sum = 0.f;
        #pragma unroll
        for (int o = 0; o < 16; o++) { e[o] = __expf(e[o] - mx); sum += e[o]; }
        float inv = 1.0f / sum;
        float ow0[16], ow1[16], ow2[16], ow3[16];
        #pragma unroll
        for (int o = 0; o < 16; o++) {
            float v = e[o] * inv;
            ow0[o] = __shfl_sync(0xffffffffu, v, 0, 4);
            ow1[o] = __shfl_sync(0xffffffffu, v, 1, 4);
            ow2[o] = __shfl_sync(0xffffffffu, v, 2, 4);
            ow3[o] = __shfl_sync(0xffffffffu, v, 3, 4);
        }
        float4* out4 = ((float4*)out) + r0 * 128;
        #pragma unroll
        for (int jj = 0; jj < 4; jj++) {
            int j = jj*32 + lane;
            float4 a0 = {0,0,0,0}, a1 = {0,0,0,0}, a2 = {0,0,0,0}, a3 = {0,0,0,0};
            #pragma unroll
            for (int o = 0; o < 16; o++) {
                float4 kv = op4[o*128 + j];
                a0.x += ow0[o]*kv.x; a0.y += ow0[o]*kv.y; a0.z += ow0[o]*kv.z; a0.w += ow0[o]*kv.w;
                a1.x += ow1[o]*kv.x; a1.y += ow1[o]*kv.y; a1.z += ow1[o]*kv.z; a1.w += ow1[o]*kv.w;
                a2.x += ow2[o]*kv.x; a2.y += ow2[o]*kv.y; a2.z += ow2[o]*kv.z; a2.w += ow2[o]*kv.w;
                a3.x += ow3[o]*kv.x; a3.y += ow3[o]*kv.y; a3.z += ow3[o]*kv.z; a3.w += ow3[o]*kv.w;
            }
            out4[j] = a0; out4[128 + j] = a1; out4[256 + j] = a2; out4[384 + j] = a3;
        }
    }
}

// ---------------------------------------------------------------------------
extern "C" void kernel_launch(void* const* d_in, const int* in_sizes, int n_in,
                              void* d_out, int out_size) {
    const float* x     = (const float*)d_in[0];
    const float* Wv    = (const float*)d_in[1];
    const float* bv    = (const float*)d_in[2];
    const float* Wk    = (const float*)d_in[3];
    const float* bk    = (const float*)d_in[4];
    const float* Wq_op = (const float*)d_in[5];
    const float* bq_op = (const float*)d_in[6];
    const float* ops   = (const float*)d_in[7];
    (void)in_sizes; (void)n_in;
    float* out = (float*)d_out;
    float* oq_out = (out_size >= Bq*Sq*Hq + Oq*Hq) ? out + (size_t)Bq*Sq*Hq : nullptr;

    kzero<<<34, 256>>>();
    k0a<<<dim3(8, 16), 512>>>(Wq_op, ops);
    k0b<<<dim3(16, 4), 128>>>(Wk, bk, bq_op, oq_out);
    k1<<<BSq/32, 256>>>(x);
    k2<<<dim3(8, 16), 256>>>(x, ops);
    ksum<<<128, 256>>>();
    k3<<<dim3(16, 16), 128>>>(Wv, bv);
    k4<<<dim3(32, 16), 256>>>(out);
}